// round 9
// baseline (speedup 1.0000x reference)
#include <cuda_runtime.h>

// ExtractLearnableSlices — LSU-slot-optimized: pairs smem (1 LDS.64/output),
// float4 output stores, one head x 4 batches per block.
//   x: (B=64, C=64, L=16384) f32
//   channel_params/offset_params: (128,) f32
//   out: (B=64, N=128, W=512) f32
//
// v[l] = xf[l] + wc*(xc[l]-xf[l]) (fused channel lerp, window of 520 around
// floor(t0)). smem holds PAIRS P[e] = (v[e], v[e+1]) with padding
// float_off(e) = 2e + 4*(e>>4) (16B-aligned stores, <=2-way LDS conflicts).
// Epilogue: out[j] = p.x + wt*(p.y-p.x), one LDS.64 + shared idx across 4
// batches, one STG.128 per 4 outputs. All FP expressions identical to R4.

#define B_DIM   64
#define C_DIM   64
#define L_DIM   16384
#define N_HEADS 128
#define WIDTH   512

#define THREADS 128
#define NB      4
#define PAD_WIN 1168   // floats per padded pairs window (max float idx 1161)

__device__ __forceinline__ int pair_off(int e) {   // float offset of P[e]
    return 2 * e + ((e >> 4) << 2);
}

__global__ __launch_bounds__(THREADS) void extract_slices_kernel(
    const float* __restrict__ x,
    const float* __restrict__ channel_params,
    const float* __restrict__ offset_params,
    float* __restrict__ out)
{
    __shared__ float P[NB][PAD_WIN];

    const int tid = threadIdx.x;        // 0..127
    const int i   = blockIdx.x;         // head
    const int b0  = blockIdx.y * NB;    // first batch

    // ---- per-head params (exact same math as R4) ----
    const float cp = __ldg(&channel_params[i]);
    const float op = __ldg(&offset_params[i]);

    const float sc      = 1.0f / (1.0f + expf(-cp));
    const float desired = sc * (float)(C_DIM - 1);
    const int   fc      = (int)desired;
    const int   cc      = min(fc + 1, C_DIM - 1);
    const float wc      = desired - (float)fc;

    const float so  = 1.0f / (1.0f + expf(-op));
    const float t0  = so * (float)(L_DIM - WIDTH);
    const int   pf0 = (int)t0;
    const int   l0  = (pf0 - 1) & ~3;

    const int xfo = fc * L_DIM + l0;
    const int xco = cc * L_DIM + l0;

    // ---- staging loads: f4 window slice + 1 extra scalar, all NB batches ----
    float4 a[NB], c[NB];
    float  as[NB], cs[NB];      // element 4*tid+4
    #pragma unroll
    for (int bb = 0; bb < NB; ++bb) {
        const size_t base = (size_t)(b0 + bb) * (size_t)(C_DIM * L_DIM);
        const float* __restrict__ xf = x + base + xfo;
        const float* __restrict__ xc = x + base + xco;
        a[bb]  = ((const float4*)xf)[tid];
        c[bb]  = ((const float4*)xc)[tid];
        as[bb] = xf[4 * tid + 4];
        cs[bb] = xc[4 * tid + 4];
    }
    // tail (elements 512..519): tid 0 -> e 512..515 (+scalar 516), tid 1 -> e 516..519
    float4 ta, tc; float tas = 0.0f, tcs = 0.0f;
    const bool tail = (tid < 2);
    if (tail) {
        const size_t base = (size_t)b0 * (size_t)(C_DIM * L_DIM); // reuse bb=0 later per-batch
        (void)base;
    }

    const int fb = 8 * tid + ((tid >> 2) << 2);   // pair_off(4*tid)

    #pragma unroll
    for (int bb = 0; bb < NB; ++bb) {
        // fused channel lerp (identical expressions to prior rounds)
        const float v0 = a[bb].x + wc * (c[bb].x - a[bb].x);
        const float v1 = a[bb].y + wc * (c[bb].y - a[bb].y);
        const float v2 = a[bb].z + wc * (c[bb].z - a[bb].z);
        const float v3 = a[bb].w + wc * (c[bb].w - a[bb].w);
        const float v4 = as[bb] + wc * (cs[bb] - as[bb]);

        float4* __restrict__ dst = (float4*)&P[bb][fb];
        dst[0] = make_float4(v0, v1, v1, v2);
        dst[1] = make_float4(v2, v3, v3, v4);
    }

    // tail pairs: per batch, threads 0/1 cover P[512..517]
    if (tail) {
        #pragma unroll
        for (int bb = 0; bb < NB; ++bb) {
            const size_t base = (size_t)(b0 + bb) * (size_t)(C_DIM * L_DIM);
            const float* __restrict__ xf = x + base + xfo;
            const float* __restrict__ xc = x + base + xco;
            const int e0 = 512 + 4 * tid;            // 512 or 516
            ta = ((const float4*)xf)[128 + tid];
            tc = ((const float4*)xc)[128 + tid];
            const float v0 = ta.x + wc * (tc.x - ta.x);
            const float v1 = ta.y + wc * (tc.y - ta.y);
            const float v2 = ta.z + wc * (tc.z - ta.z);
            const float v3 = ta.w + wc * (tc.w - ta.w);
            float4* __restrict__ dst = (float4*)&P[bb][pair_off(e0)];
            if (tid == 0) {
                tas = xf[516]; tcs = xc[516];
                const float v4 = tas + wc * (tcs - tas);
                dst[0] = make_float4(v0, v1, v1, v2);
                dst[1] = make_float4(v2, v3, v3, v4);
            } else {
                // e0 = 516: only P[516], P[517] needed (idx <= 516)
                dst[0] = make_float4(v0, v1, v1, v2);
            }
        }
    }
    __syncthreads();

    // ---- epilogue: idx/wt once per j, 1 LDS.64 + lerp per (j, batch) ----
    float wt[4]; int fidx[4];
    #pragma unroll
    for (int m = 0; m < 4; ++m) {
        const int   j   = 4 * tid + m;
        const float pos = t0 + (float)j;     // exact ref f32 math
        const int   pf  = (int)pos;          // floor (positive)
        wt[m] = pos - (float)pf;
        fidx[m] = pair_off(pf - l0);         // idx in [0, 516]
    }

    const size_t ostride = (size_t)N_HEADS * WIDTH;
    float* __restrict__ obase = out + ((size_t)b0 * N_HEADS + i) * WIDTH + 4 * tid;

    #pragma unroll
    for (int bb = 0; bb < NB; ++bb) {
        const float* __restrict__ Pw = P[bb];
        float4 o;
        {
            const float2 p = *(const float2*)&Pw[fidx[0]];
            o.x = p.x + wt[0] * (p.y - p.x);
        }
        {
            const float2 p = *(const float2*)&Pw[fidx[1]];
            o.y = p.x + wt[1] * (p.y - p.x);
        }
        {
            const float2 p = *(const float2*)&Pw[fidx[2]];
            o.z = p.x + wt[2] * (p.y - p.x);
        }
        {
            const float2 p = *(const float2*)&Pw[fidx[3]];
            o.w = p.x + wt[3] * (p.y - p.x);
        }
        *(float4*)(obase + bb * ostride) = o;
    }
}

extern "C" void kernel_launch(void* const* d_in, const int* in_sizes, int n_in,
                              void* d_out, int out_size)
{
    const float* x  = (const float*)d_in[0];
    const float* ch = (const float*)d_in[1];
    const float* of = (const float*)d_in[2];
    float* out = (float*)d_out;

    dim3 grid(N_HEADS, B_DIM / NB);
    extract_slices_kernel<<<grid, THREADS>>>(x, ch, of, out);
}

// round 10
// speedup vs baseline: 1.2536x; 1.2536x over previous
#include <cuda_runtime.h>

// ExtractLearnableSlices — register-direct: no smem, no barrier, no LDS.
//   x: (B=64, C=64, L=16384) f32
//   channel_params/offset_params: (128,) f32
//   out: (B=64, N=128, W=512) f32
//
// l0 = pf0 & ~3, d = pf0 - l0 in {0..3} (uniform per head). Thread t owns
// outputs j = 4t..4t+3, which need window elements d+j .. d+j+4 — all inside
// the 8 elements [4t, 4t+7] loaded as two overlapping float4 per channel.
// switch(d) keeps element selection compile-time. Time lerp uses the chord
// [pf0+j, pf0+j+1] evaluated at pos = fl(t0+j) with signed wt, which equals
// the reference except for O(ulp) chord-extension at floor-rounding wobble.

#define B_DIM   64
#define C_DIM   64
#define L_DIM   16384
#define N_HEADS 128
#define WIDTH   512
#define THREADS 128
#define NB      4

struct Quad { float4 fA, fB, cA, cB; };

__device__ __forceinline__ Quad load_quad(const float* __restrict__ x,
                                          size_t base, int xfo, int xco, int tid)
{
    Quad q;
    const float4* __restrict__ f4 = (const float4*)(x + base + xfo);
    const float4* __restrict__ c4 = (const float4*)(x + base + xco);
    q.fA = f4[tid];
    q.fB = f4[tid + 1];
    q.cA = c4[tid];
    q.cB = c4[tid + 1];
    return q;
}

template<int E>
__device__ __forceinline__ float elem(const float4& A, const float4& B) {
    if constexpr (E == 0) return A.x;
    else if constexpr (E == 1) return A.y;
    else if constexpr (E == 2) return A.z;
    else if constexpr (E == 3) return A.w;
    else if constexpr (E == 4) return B.x;
    else if constexpr (E == 5) return B.y;
    else if constexpr (E == 6) return B.z;
    else return B.w;
}

template<int D>
__device__ __forceinline__ float4 tile_out(const Quad& q, float wc, const float* wt)
{
    // channel lerp at window elements D..D+4 (D+4 <= 7)
    const float a0 = elem<D + 0>(q.fA, q.fB), c0 = elem<D + 0>(q.cA, q.cB);
    const float a1 = elem<D + 1>(q.fA, q.fB), c1 = elem<D + 1>(q.cA, q.cB);
    const float a2 = elem<D + 2>(q.fA, q.fB), c2 = elem<D + 2>(q.cA, q.cB);
    const float a3 = elem<D + 3>(q.fA, q.fB), c3 = elem<D + 3>(q.cA, q.cB);
    const float a4 = elem<D + 4>(q.fA, q.fB), c4 = elem<D + 4>(q.cA, q.cB);

    const float v0 = a0 + wc * (c0 - a0);
    const float v1 = a1 + wc * (c1 - a1);
    const float v2 = a2 + wc * (c2 - a2);
    const float v3 = a3 + wc * (c3 - a3);
    const float v4 = a4 + wc * (c4 - a4);

    float4 o;
    o.x = v0 + wt[0] * (v1 - v0);
    o.y = v1 + wt[1] * (v2 - v1);
    o.z = v2 + wt[2] * (v3 - v2);
    o.w = v3 + wt[3] * (v4 - v3);
    return o;
}

template<int D>
__device__ __forceinline__ void run(const float* __restrict__ x,
                                    float* __restrict__ obase,
                                    size_t xstride, size_t ostride,
                                    size_t base0, int xfo, int xco,
                                    float wc, const float* wt, int tid)
{
    // 2-deep pipelined over NB=4 batches
    Quad q0 = load_quad(x, base0,               xfo, xco, tid);
    Quad q1 = load_quad(x, base0 +     xstride, xfo, xco, tid);

    Quad q2 = load_quad(x, base0 + 2 * xstride, xfo, xco, tid);
    *(float4*)(obase)               = tile_out<D>(q0, wc, wt);

    Quad q3 = load_quad(x, base0 + 3 * xstride, xfo, xco, tid);
    *(float4*)(obase +     ostride) = tile_out<D>(q1, wc, wt);

    *(float4*)(obase + 2 * ostride) = tile_out<D>(q2, wc, wt);
    *(float4*)(obase + 3 * ostride) = tile_out<D>(q3, wc, wt);
}

__global__ __launch_bounds__(THREADS) void extract_slices_kernel(
    const float* __restrict__ x,
    const float* __restrict__ channel_params,
    const float* __restrict__ offset_params,
    float* __restrict__ out)
{
    const int tid = threadIdx.x;        // 0..127
    const int i   = blockIdx.x;         // head
    const int b0  = blockIdx.y * NB;    // first batch

    // ---- per-head params (same math as all passing rounds) ----
    const float cp = __ldg(&channel_params[i]);
    const float op = __ldg(&offset_params[i]);

    const float sc      = 1.0f / (1.0f + expf(-cp));
    const float desired = sc * (float)(C_DIM - 1);   // > 0
    const int   fc      = (int)desired;              // floor (positive)
    const int   cc      = min(fc + 1, C_DIM - 1);
    const float wc      = desired - (float)fc;

    const float so  = 1.0f / (1.0f + expf(-op));
    const float t0  = so * (float)(L_DIM - WIDTH);   // > 0
    const int   pf0 = (int)t0;                       // floor (positive)
    const int   l0  = pf0 & ~3;                      // float4-aligned origin
    const int   d   = pf0 - l0;                      // 0..3, uniform per head

    const int xfo = fc * L_DIM + l0;
    const int xco = cc * L_DIM + l0;

    // ---- per-output signed weights vs assumed floor pf0 + j ----
    const int j0 = 4 * tid;
    float wt[4];
    #pragma unroll
    for (int m = 0; m < 4; ++m) {
        const float pos = t0 + (float)(j0 + m);      // exact ref f32 math
        wt[m] = pos - (float)(pf0 + j0 + m);         // signed chord weight
    }

    float* __restrict__ obase = out + ((size_t)b0 * N_HEADS + i) * WIDTH + j0;
    const size_t ostride = (size_t)N_HEADS * WIDTH;
    const size_t xstride = (size_t)(C_DIM * L_DIM);
    const size_t base0   = (size_t)b0 * xstride;

    switch (d) {   // uniform branch per block
        case 0:  run<0>(x, obase, xstride, ostride, base0, xfo, xco, wc, wt, tid); break;
        case 1:  run<1>(x, obase, xstride, ostride, base0, xfo, xco, wc, wt, tid); break;
        case 2:  run<2>(x, obase, xstride, ostride, base0, xfo, xco, wc, wt, tid); break;
        default: run<3>(x, obase, xstride, ostride, base0, xfo, xco, wc, wt, tid); break;
    }
}

extern "C" void kernel_launch(void* const* d_in, const int* in_sizes, int n_in,
                              void* d_out, int out_size)
{
    const float* x  = (const float*)d_in[0];
    const float* ch = (const float*)d_in[1];
    const float* of = (const float*)d_in[2];
    float* out = (float*)d_out;

    dim3 grid(N_HEADS, B_DIM / NB);
    extract_slices_kernel<<<grid, THREADS>>>(x, ch, of, out);
}